// round 10
// baseline (speedup 1.0000x reference)
#include <cuda_runtime.h>
#include <cuda_fp16.h>
#include <cstdint>

// Cosine self-attention, fp16 mma.sync m16n8k16, symmetric GEMM1,
// cp.async 3-stage pipeline, rowsum fused into GEMM2.
// R9 change: 256-thread CTAs (8 warps, 64x32 warp tiles) to double
// warps-per-SMSP — gemm mainloops were HMMA issue/latency bound at occ 11.7%.

#define BATCH 16
#define SEQ   2048
#define DIM   512
#define CK    32
#define NTILE 16
#define NPAIR 136

__device__ __half g_xhat[BATCH * SEQ * DIM];               // 32 MB
__device__ __half g_xT[BATCH * DIM * SEQ];                 // 32 MB
__device__ __half g_P[(size_t)BATCH * SEQ * SEQ];          // 128 MB

// ---------------- ptx helpers ----------------
__device__ __forceinline__ void mma16(float c[4], const uint32_t a[4],
                                      const uint32_t b[2]) {
    asm volatile(
        "mma.sync.aligned.m16n8k16.row.col.f32.f16.f16.f32 "
        "{%0,%1,%2,%3}, {%4,%5,%6,%7}, {%8,%9}, {%0,%1,%2,%3};"
        : "+f"(c[0]), "+f"(c[1]), "+f"(c[2]), "+f"(c[3])
        : "r"(a[0]), "r"(a[1]), "r"(a[2]), "r"(a[3]), "r"(b[0]), "r"(b[1]));
}
__device__ __forceinline__ uint32_t movmat(uint32_t a) {
    uint32_t d;
    asm("movmatrix.sync.aligned.m8n8.trans.b16 %0, %1;" : "=r"(d) : "r"(a));
    return d;
}
__device__ __forceinline__ void cp16(uint32_t dst, const void* src) {
    asm volatile("cp.async.cg.shared.global [%0], [%1], 16;"
                 :: "r"(dst), "l"(src) : "memory");
}
__device__ __forceinline__ void cp_commit() {
    asm volatile("cp.async.commit_group;" ::: "memory");
}

// ---------------- kernel: xhat (f32 -> normalized half) ----------------
__global__ void xhat_kernel(const float* __restrict__ x) {
    int row  = blockIdx.x * 8 + (threadIdx.x >> 5);
    int lane = threadIdx.x & 31;
    const float4* xr = (const float4*)x + (size_t)row * (DIM / 4);
    float4 v[4];
    float ss = 0.f;
#pragma unroll
    for (int i = 0; i < 4; i++) {
        v[i] = xr[i * 32 + lane];
        ss += v[i].x * v[i].x + v[i].y * v[i].y + v[i].z * v[i].z + v[i].w * v[i].w;
    }
#pragma unroll
    for (int m = 16; m; m >>= 1) ss += __shfl_xor_sync(0xffffffffu, ss, m);
    float s = 1.0f / sqrtf(ss);
    uint2* o = (uint2*)(g_xhat + (size_t)row * DIM);
#pragma unroll
    for (int i = 0; i < 4; i++) {
        __half2 h0 = __floats2half2_rn(v[i].x * s, v[i].y * s);
        __half2 h1 = __floats2half2_rn(v[i].z * s, v[i].w * s);
        uint2 u;
        u.x = *(uint32_t*)&h0;
        u.y = *(uint32_t*)&h1;
        o[i * 32 + lane] = u;
    }
}

// ---------------- kernel: xT (per-batch transpose, f32 -> half) ----------
__global__ void xT_kernel(const float* __restrict__ x) {
    __shared__ float t[32][33];
    const int b = blockIdx.z, s0 = blockIdx.x * 32, d0 = blockIdx.y * 32;
    const int tx = threadIdx.x, ty = threadIdx.y;
#pragma unroll
    for (int i = 0; i < 4; i++)
        t[ty + 8 * i][tx] = x[((size_t)b * SEQ + s0 + ty + 8 * i) * DIM + d0 + tx];
    __syncthreads();
#pragma unroll
    for (int i = 0; i < 4; i++)
        g_xT[((size_t)b * DIM + d0 + ty + 8 * i) * SEQ + s0 + tx] =
            __float2half(t[tx][ty + 8 * i]);
}

// ------- GEMM core: 128x128 CTA, 8 warps (64x32 tiles), cp.async 3-stage ----
// smem layouts (u32 units):
//   A: ((ks*8  + mgrp)*4 + reg)*32 + lane     mgrp = global 16-row group 0..7
//   B: ((ks*16 + ngrp)*2 + reg)*32 + lane     ngrp = global  8-col group 0..15
#define CHUNK_U32 2048
#define STAGE_B   8192

template <bool SUMROWS>
__device__ __forceinline__ void compute_chunk(const uint32_t* Abuf,
                                              const uint32_t* Bbuf,
                                              float c[4][4][4], int wm, int wn,
                                              int lane, float* sumA) {
#pragma unroll
    for (int ks = 0; ks < 2; ks++) {
        uint32_t a[4][4], b[4][2];
#pragma unroll
        for (int mt = 0; mt < 4; mt++) {
            const uint32_t* p = Abuf + ((ks * 8 + wm * 4 + mt) * 4) * 32 + lane;
#pragma unroll
            for (int j = 0; j < 4; j++) a[mt][j] = p[j * 32];
        }
#pragma unroll
        for (int nt = 0; nt < 4; nt++) {
            const uint32_t* p = Bbuf + ((ks * 16 + wn * 4 + nt) * 2) * 32 + lane;
#pragma unroll
            for (int j = 0; j < 2; j++) b[nt][j] = p[j * 32];
        }
        if (SUMROWS && wn == 0) {
#pragma unroll
            for (int mt = 0; mt < 4; mt++) {
                float2 f0 = __half22float2(*(__half2*)&a[mt][0]);
                float2 f2 = __half22float2(*(__half2*)&a[mt][2]);
                sumA[mt * 2] += (f0.x + f0.y) + (f2.x + f2.y);
                float2 f1 = __half22float2(*(__half2*)&a[mt][1]);
                float2 f3 = __half22float2(*(__half2*)&a[mt][3]);
                sumA[mt * 2 + 1] += (f1.x + f1.y) + (f3.x + f3.y);
            }
        }
#pragma unroll
        for (int mt = 0; mt < 4; mt++)
#pragma unroll
            for (int nt = 0; nt < 4; nt++)
                mma16(c[mt][nt], a[mt], b[nt]);
    }
}

// Threads 0..127 load A row (tid), threads 128..255 load B row (tid-128).
template <bool SUMROWS>
__device__ __forceinline__ void gemm_main(const uint4* Ag, const uint4* Bg, int T,
                                          float c[4][4][4], uint32_t* As,
                                          uint32_t* Bs, int tid, int wm, int wn,
                                          int lane, float* sumA) {
    const int row   = tid & 127;
    const bool isA  = tid < 128;
    const int mtile = row >> 4;
    const int r0    = (row >> 3) & 1;
    const int la4   = (row & 7) * 4;
    const int ntile = row >> 3;
    uint32_t off[4];
#pragma unroll
    for (int q = 0; q < 4; q++) {
        const int ks = q >> 1;
        if (isA) {
            const int regA = (q & 1) * 2 + r0;
            off[q] = (((ks * 8 + mtile) * 4 + regA) * 32 + la4) * 4;
        } else {
            const int regB = q & 1;
            off[q] = (((ks * 16 + ntile) * 2 + regB) * 32 + la4) * 4;
        }
    }
    const uint32_t base = isA ? (uint32_t)__cvta_generic_to_shared(As)
                              : (uint32_t)__cvta_generic_to_shared(Bs);
    const uint4* G = isA ? Ag + (size_t)row * (SUMROWS ? SEQ : 0, 0)  // unused
                         : nullptr;
    (void)G;
    const uint4* Gsrc = isA ? Ag : Bg;   // already offset per-row by caller

    auto issue = [&](int t) {
        const uint32_t s = (uint32_t)(t % 3) * STAGE_B;
#pragma unroll
        for (int q = 0; q < 4; q++) cp16(base + s + off[q], &Gsrc[t * 4 + q]);
        cp_commit();
    };

    issue(0);
    if (T > 1) issue(1);
    for (int t = 0; t < T; t++) {
        if (t + 1 < T)
            asm volatile("cp.async.wait_group 1;" ::: "memory");
        else
            asm volatile("cp.async.wait_group 0;" ::: "memory");
        __syncthreads();
        if (t + 2 < T) issue(t + 2);
        const int s = t % 3;
        compute_chunk<SUMROWS>(As + s * CHUNK_U32, Bs + s * CHUNK_U32, c, wm, wn,
                               lane, sumA);
    }
}

// ------- kernel: GEMM1 (symmetric)  P = half(exp(xhat xhat^T - 1)) ---------
__global__ __launch_bounds__(256, 2) void gemm1_kernel() {
    __shared__ __align__(16) uint32_t As[3 * CHUNK_U32];
    __shared__ __align__(16) uint32_t Bs[3 * CHUNK_U32];
    const int b = blockIdx.z;
    const int idx = blockIdx.x;
    int ti = (int)(NTILE + 0.5f -
                   sqrtf((NTILE + 0.5f) * (NTILE + 0.5f) - 2.0f * idx - 0.25f));
    while (ti * NTILE - ti * (ti - 1) / 2 > idx) ti--;
    while ((ti + 1) * NTILE - (ti + 1) * ti / 2 <= idx) ti++;
    const int tj = ti + (idx - (ti * NTILE - ti * (ti - 1) / 2));
    const int m0 = ti * 128, n0 = tj * 128;

    const int tid = threadIdx.x, wid = tid >> 5, lane = tid & 31;
    const int wm = wid >> 2, wn = wid & 3;
    const int row = tid & 127;

    const __half* Xb = g_xhat + (size_t)b * SEQ * DIM;
    const uint4* Ag = (const uint4*)(Xb + (size_t)(m0 + row) * DIM);
    const uint4* Bg = (const uint4*)(Xb + (size_t)(n0 + row) * DIM);

    float c[4][4][4];
#pragma unroll
    for (int i = 0; i < 4; i++)
#pragma unroll
        for (int j = 0; j < 4; j++)
#pragma unroll
            for (int k = 0; k < 4; k++) c[i][j][k] = 0.f;
    float dummy[8];

    gemm_main<false>(Ag, Bg, DIM / CK, c, As, Bs, tid, wm, wn, lane, dummy);

    const int row0 = m0 + wm * 64 + (lane >> 2);
    const int col0 = n0 + wn * 32 + (lane & 3) * 2;
    const bool mirror = (ti != tj);
#pragma unroll
    for (int mt = 0; mt < 4; mt++) {
#pragma unroll
        for (int nt = 0; nt < 4; nt++) {
            const int r1 = row0 + mt * 16;
            const int cc = col0 + nt * 8;
            __half2 h0 = __floats2half2_rn(__expf(c[mt][nt][0] - 1.0f),
                                           __expf(c[mt][nt][1] - 1.0f));
            __half2 h1 = __floats2half2_rn(__expf(c[mt][nt][2] - 1.0f),
                                           __expf(c[mt][nt][3] - 1.0f));
            *(__half2*)&g_P[((size_t)b * SEQ + r1) * SEQ + cc] = h0;
            *(__half2*)&g_P[((size_t)b * SEQ + r1 + 8) * SEQ + cc] = h1;
            if (mirror) {
                uint32_t t0 = movmat(*(uint32_t*)&h0);
                uint32_t t1 = movmat(*(uint32_t*)&h1);
                const int rm = n0 + wn * 32 + nt * 8 + (lane >> 2);
                const int cm = m0 + wm * 64 + mt * 16 + (lane & 3) * 2;
                *(uint32_t*)&g_P[((size_t)b * SEQ + rm) * SEQ + cm] = t0;
                *(uint32_t*)&g_P[((size_t)b * SEQ + rm) * SEQ + cm + 8] = t1;
            }
        }
    }
}

// ------- kernel: GEMM2  out = (P @ x) / rowsum(P), rowsum in-kernel --------
__global__ __launch_bounds__(256, 2) void gemm2_kernel(float* __restrict__ out) {
    __shared__ __align__(16) uint32_t As[3 * CHUNK_U32];
    __shared__ __align__(16) uint32_t Bs[3 * CHUNK_U32];
    const int b = blockIdx.z, m0 = blockIdx.y * 128, n0 = blockIdx.x * 128;
    const int tid = threadIdx.x, wid = tid >> 5, lane = tid & 31;
    const int wm = wid >> 2, wn = wid & 3;
    const int row = tid & 127;

    const uint4* Ag = (const uint4*)(g_P + ((size_t)b * SEQ + m0 + row) * SEQ);
    const uint4* Bg = (const uint4*)(g_xT + ((size_t)b * DIM + n0 + row) * SEQ);

    float c[4][4][4];
#pragma unroll
    for (int i = 0; i < 4; i++)
#pragma unroll
        for (int j = 0; j < 4; j++)
#pragma unroll
            for (int k = 0; k < 4; k++) c[i][j][k] = 0.f;
    float sumA[8];
#pragma unroll
    for (int i = 0; i < 8; i++) sumA[i] = 0.f;

    gemm_main<true>(Ag, Bg, SEQ / CK, c, As, Bs, tid, wm, wn, lane, sumA);

    // reduce row sums across the 4 lanes sharing each row
#pragma unroll
    for (int i = 0; i < 8; i++) {
        sumA[i] += __shfl_xor_sync(0xffffffffu, sumA[i], 1);
        sumA[i] += __shfl_xor_sync(0xffffffffu, sumA[i], 2);
    }
    __syncthreads();
    float* rs = (float*)As;
    if (wn == 0 && (lane & 3) == 0) {
#pragma unroll
        for (int mt = 0; mt < 4; mt++) {
            rs[wm * 64 + mt * 16 + (lane >> 2)]     = sumA[mt * 2];
            rs[wm * 64 + mt * 16 + 8 + (lane >> 2)] = sumA[mt * 2 + 1];
        }
    }
    __syncthreads();

    const int row0 = m0 + wm * 64 + (lane >> 2);
    const int col0 = n0 + wn * 32 + (lane & 3) * 2;
#pragma unroll
    for (int mt = 0; mt < 4; mt++) {
        const int lr = wm * 64 + mt * 16 + (lane >> 2);
        const float ri0 = 1.0f / rs[lr];
        const float ri1 = 1.0f / rs[lr + 8];
        const int r1 = row0 + mt * 16;
#pragma unroll
        for (int nt = 0; nt < 4; nt++) {
            const int cc = col0 + nt * 8;
            float2 w0, w1;
            w0.x = c[mt][nt][0] * ri0;
            w0.y = c[mt][nt][1] * ri0;
            w1.x = c[mt][nt][2] * ri1;
            w1.y = c[mt][nt][3] * ri1;
            *(float2*)&out[((size_t)b * SEQ + r1) * DIM + cc] = w0;
            *(float2*)&out[((size_t)b * SEQ + r1 + 8) * DIM + cc] = w1;
        }
    }
}

// ---------------- launch ----------------
extern "C" void kernel_launch(void* const* d_in, const int* in_sizes, int n_in,
                              void* d_out, int out_size) {
    const float* x = (const float*)d_in[0];
    float* out = (float*)d_out;

    xhat_kernel<<<BATCH * SEQ / 8, 256>>>(x);
    xT_kernel<<<dim3(SEQ / 32, DIM / 32, BATCH), dim3(32, 8)>>>(x);
    gemm1_kernel<<<dim3(NPAIR, 1, BATCH), 256>>>();
    gemm2_kernel<<<dim3(DIM / 128, SEQ / 128, BATCH), 256>>>(out);
}

// round 12
// speedup vs baseline: 1.8141x; 1.8141x over previous
#include <cuda_runtime.h>
#include <cuda_fp16.h>
#include <cstdint>

// Cosine self-attention, fp16 mma.sync m16n8k16.
// R10 finding: 16B cp.async fill ops (LDGSTS rt=8/SMSP) bound the GEMMs.
// R12: all operand tiles stored in gmem in the EXACT fragment-ordered smem
// image of the passing R10 kernel; fill = one contiguous 8KB cp.async.bulk
// per operand per chunk. compute_chunk / rowsum / mirror logic unchanged.
//   g_xhA/g_xhB : xhat in A-/B-fragment image (GEMM1 reads both)
//   g_xT        : x^T in B-fragment image     (GEMM2 B)
//   g_P         : P in A-fragment image        (GEMM1 writes, GEMM2 A)

#define BATCH 16
#define SEQ   2048
#define DIM   512
#define NTILE 16
#define NPAIR 136
#define TILE_U32 2048                 // 128 rows x 32 halves = 8KB
#define TILE_B   8192
#define STAGE_U32 4096                // A + B
#define STAGE_B   16384
#define SMEM_DYN  49152               // 3 stages

__device__ __align__(256) uint32_t g_xhA[(size_t)BATCH * 16 * 16 * TILE_U32];
__device__ __align__(256) uint32_t g_xhB[(size_t)BATCH * 16 * 16 * TILE_U32];
__device__ __align__(256) uint32_t g_xT[(size_t)BATCH * 4 * 64 * TILE_U32];
__device__ __align__(256) uint32_t g_P[(size_t)BATCH * 16 * 64 * TILE_U32];

// ---------------- ptx helpers ----------------
__device__ __forceinline__ void mma16(float c[4], const uint32_t a[4],
                                      const uint32_t b[2]) {
    asm volatile(
        "mma.sync.aligned.m16n8k16.row.col.f32.f16.f16.f32 "
        "{%0,%1,%2,%3}, {%4,%5,%6,%7}, {%8,%9}, {%0,%1,%2,%3};"
        : "+f"(c[0]), "+f"(c[1]), "+f"(c[2]), "+f"(c[3])
        : "r"(a[0]), "r"(a[1]), "r"(a[2]), "r"(a[3]), "r"(b[0]), "r"(b[1]));
}
__device__ __forceinline__ uint32_t movmat(uint32_t a) {
    uint32_t d;
    asm("movmatrix.sync.aligned.m8n8.trans.b16 %0, %1;" : "=r"(d) : "r"(a));
    return d;
}
__device__ __forceinline__ void mbar_init(uint32_t mbar, uint32_t cnt) {
    asm volatile("mbarrier.init.shared.b64 [%0], %1;" :: "r"(mbar), "r"(cnt)
                 : "memory");
}
__device__ __forceinline__ void mbar_expect(uint32_t mbar, uint32_t bytes) {
    asm volatile("mbarrier.arrive.expect_tx.shared.b64 _, [%0], %1;"
                 :: "r"(mbar), "r"(bytes) : "memory");
}
__device__ __forceinline__ void mbar_wait(uint32_t mbar, uint32_t parity) {
    asm volatile(
        "{\n\t.reg .pred P1;\n\t"
        "WL_%=:\n\t"
        "mbarrier.try_wait.parity.acquire.cta.shared::cta.b64 P1, [%0], %1, 0x989680;\n\t"
        "@P1 bra.uni WD_%=;\n\t"
        "bra.uni WL_%=;\n\t"
        "WD_%=:\n\t}"
        :: "r"(mbar), "r"(parity) : "memory");
}
__device__ __forceinline__ void bulk_cp(uint32_t dst, const void* src,
                                        uint32_t bytes, uint32_t mbar) {
    asm volatile(
        "cp.async.bulk.shared::cluster.global.mbarrier::complete_tx::bytes "
        "[%0], [%1], %2, [%3];"
        :: "r"(dst), "l"(src), "r"(bytes), "r"(mbar) : "memory");
}
__device__ __forceinline__ void fence_async() {
    asm volatile("fence.proxy.async.shared::cta;" ::: "memory");
}

// ---------- fragment-image index helpers (match R10 sts_stage exactly) -----
// A image, element uint4 (row r 0..127, q 0..3 = halves [8q,8q+8)):
__device__ __forceinline__ int a_img_u4(int r, int q) {
    return (((q >> 1) * 8 + (r >> 4)) * 4 + (q & 1) * 2 + ((r >> 3) & 1)) * 32 +
           (r & 7) * 4;
}
// B image:
__device__ __forceinline__ int b_img_u4(int n, int q) {
    return (((q >> 1) * 16 + (n >> 3)) * 2 + (q & 1)) * 32 + (n & 7) * 4;
}

// ---------------- kernel: xhat -> A-image + B-image tiles ------------------
__global__ void xhat_kernel(const float* __restrict__ x) {
    const int grow = blockIdx.x * 8 + (threadIdx.x >> 5);
    const int lane = threadIdx.x & 31;
    // lane covers floats [16*lane, 16*lane+16) of its row
    const float4* src = (const float4*)(x + (size_t)grow * DIM) + lane * 4;
    float4 v[4];
    float ss = 0.f;
#pragma unroll
    for (int i = 0; i < 4; i++) {
        v[i] = src[i];
        ss += v[i].x * v[i].x + v[i].y * v[i].y + v[i].z * v[i].z + v[i].w * v[i].w;
    }
#pragma unroll
    for (int m = 16; m; m >>= 1) ss += __shfl_xor_sync(0xffffffffu, ss, m);
    const float s = 1.0f / sqrtf(ss);
    uint4 U[2];
#pragma unroll
    for (int u = 0; u < 2; u++) {
        __half2 h0 = __floats2half2_rn(v[2 * u].x * s, v[2 * u].y * s);
        __half2 h1 = __floats2half2_rn(v[2 * u].z * s, v[2 * u].w * s);
        __half2 h2 = __floats2half2_rn(v[2 * u + 1].x * s, v[2 * u + 1].y * s);
        __half2 h3 = __floats2half2_rn(v[2 * u + 1].z * s, v[2 * u + 1].w * s);
        U[u].x = *(uint32_t*)&h0; U[u].y = *(uint32_t*)&h1;
        U[u].z = *(uint32_t*)&h2; U[u].w = *(uint32_t*)&h3;
    }
    const int b = grow >> 11, r = grow & 2047, rb = r >> 7, rr = r & 127;
    const int c = lane >> 1;
    uint32_t* tA = g_xhA + ((size_t)((b * 16 + rb) * 16 + c)) * TILE_U32;
    uint32_t* tB = g_xhB + ((size_t)((b * 16 + rb) * 16 + c)) * TILE_U32;
#pragma unroll
    for (int u = 0; u < 2; u++) {
        const int q = (lane & 1) * 2 + u;
        *(uint4*)(tA + a_img_u4(rr, q)) = U[u];
        *(uint4*)(tB + b_img_u4(rr, q)) = U[u];
    }
}

// ---------------- kernel: xT -> B-image tiles ------------------------------
__global__ void xT_kernel(const float* __restrict__ x) {
    __shared__ float t[32][33];
    const int b = blockIdx.z, s0 = blockIdx.x * 32, d0 = blockIdx.y * 32;
    const int tx = threadIdx.x, ty = threadIdx.y;
#pragma unroll
    for (int i = 0; i < 4; i++)
        t[ty + 8 * i][tx] = x[((size_t)b * SEQ + s0 + ty + 8 * i) * DIM + d0 + tx];
    __syncthreads();
    const int c  = s0 >> 5;
    const int nb = d0 >> 7;
    const int n  = (d0 & 127) + tx;
    uint32_t* tile = g_xT + ((size_t)((b * 4 + nb) * 64 + c)) * TILE_U32;
#pragma unroll
    for (int i = 0; i < 2; i++) {
        const int u = ty + 8 * i;      // s-pair index: halves (2u, 2u+1)
        __half2 hv = __floats2half2_rn(t[2 * u][tx], t[2 * u + 1][tx]);
        const int q = u >> 2;
        const int idx = (((q >> 1) * 16 + (n >> 3)) * 2 + (q & 1)) * 32 +
                        (n & 7) * 4 + (u & 3);
        tile[idx] = *(uint32_t*)&hv;
    }
}

// ------------- GEMM core: bulk-fill pipeline + R10 fragment reads ----------
template <bool SUMROWS>
__device__ __forceinline__ void compute_chunk(const uint32_t* Abuf,
                                              const uint32_t* Bbuf,
                                              float c[4][4][4], int wm, int wn,
                                              int lane, float* sumA) {
#pragma unroll
    for (int ks = 0; ks < 2; ks++) {
        uint32_t a[4][4], b[4][2];
#pragma unroll
        for (int mt = 0; mt < 4; mt++) {
            const uint32_t* p = Abuf + ((ks * 8 + wm * 4 + mt) * 4) * 32 + lane;
#pragma unroll
            for (int j = 0; j < 4; j++) a[mt][j] = p[j * 32];
        }
#pragma unroll
        for (int nt = 0; nt < 4; nt++) {
            const uint32_t* p = Bbuf + ((ks * 16 + wn * 4 + nt) * 2) * 32 + lane;
#pragma unroll
            for (int j = 0; j < 2; j++) b[nt][j] = p[j * 32];
        }
        if (SUMROWS && wn == 0) {
#pragma unroll
            for (int mt = 0; mt < 4; mt++) {
                float2 f0 = __half22float2(*(__half2*)&a[mt][0]);
                float2 f2 = __half22float2(*(__half2*)&a[mt][2]);
                sumA[mt * 2] += (f0.x + f0.y) + (f2.x + f2.y);
                float2 f1 = __half22float2(*(__half2*)&a[mt][1]);
                float2 f3 = __half22float2(*(__half2*)&a[mt][3]);
                sumA[mt * 2 + 1] += (f1.x + f1.y) + (f3.x + f3.y);
            }
        }
#pragma unroll
        for (int mt = 0; mt < 4; mt++)
#pragma unroll
            for (int nt = 0; nt < 4; nt++)
                mma16(c[mt][nt], a[mt], b[nt]);
    }
}

template <bool SUMROWS>
__device__ __forceinline__ void gemm_main(const char* Abase, const char* Bbase,
                                          int T, float c[4][4][4],
                                          uint32_t* smem, uint32_t smem_u32,
                                          uint32_t mbar_u32, int tid, int wm,
                                          int wn, int lane, float* sumA) {
    uint32_t ph0 = 0, ph1 = 0, ph2 = 0;
    auto issue = [&](int t) {
        if (tid == 0) {
            const int s = t % 3;
            const uint32_t mb = mbar_u32 + s * 8;
            mbar_expect(mb, STAGE_B);
            bulk_cp(smem_u32 + s * STAGE_B, Abase + (size_t)t * TILE_B, TILE_B, mb);
            bulk_cp(smem_u32 + s * STAGE_B + TILE_B, Bbase + (size_t)t * TILE_B,
                    TILE_B, mb);
        }
    };
    issue(0);
    if (T > 1) issue(1);
    for (int t = 0; t < T; t++) {
        const int s = t % 3;
        const uint32_t mb = mbar_u32 + s * 8;
        if (s == 0)      { mbar_wait(mb, ph0); ph0 ^= 1; }
        else if (s == 1) { mbar_wait(mb, ph1); ph1 ^= 1; }
        else             { mbar_wait(mb, ph2); ph2 ^= 1; }
        __syncthreads();               // all threads done with stage (t-1)%3
        if (t + 2 < T) issue(t + 2);
        compute_chunk<SUMROWS>(smem + s * STAGE_U32,
                               smem + s * STAGE_U32 + TILE_U32, c, wm, wn, lane,
                               sumA);
    }
}

// ------- kernel: GEMM1 (symmetric)  P = half(exp(xhat xhat^T - 1)) ---------
__global__ __launch_bounds__(256, 2) void gemm1_kernel() {
    extern __shared__ __align__(128) uint32_t smem[];
    __shared__ __align__(8) unsigned long long mbars[3];
    const uint32_t smem_u32 = (uint32_t)__cvta_generic_to_shared(smem);
    const uint32_t mbar_u32 = (uint32_t)__cvta_generic_to_shared(mbars);
    const int b = blockIdx.z;
    const int idx = blockIdx.x;
    int ti = (int)(NTILE + 0.5f -
                   sqrtf((NTILE + 0.5f) * (NTILE + 0.5f) - 2.0f * idx - 0.25f));
    while (ti * NTILE - ti * (ti - 1) / 2 > idx) ti--;
    while ((ti + 1) * NTILE - (ti + 1) * ti / 2 <= idx) ti++;
    const int tj = ti + (idx - (ti * NTILE - ti * (ti - 1) / 2));

    const int tid = threadIdx.x, wid = tid >> 5, lane = tid & 31;
    const int wm = wid >> 2, wn = wid & 3;

    if (tid == 0) {
#pragma unroll
        for (int s = 0; s < 3; s++) mbar_init(mbar_u32 + s * 8, 1);
        fence_async();
    }
    __syncthreads();

    const char* Abase =
        (const char*)(g_xhA + ((size_t)((b * 16 + ti) * 16)) * TILE_U32);
    const char* Bbase =
        (const char*)(g_xhB + ((size_t)((b * 16 + tj) * 16)) * TILE_U32);

    float c[4][4][4];
#pragma unroll
    for (int i = 0; i < 4; i++)
#pragma unroll
        for (int j = 0; j < 4; j++)
#pragma unroll
            for (int k = 0; k < 4; k++) c[i][j][k] = 0.f;
    float dummy[8];

    gemm_main<false>(Abase, Bbase, DIM / 32, c, smem, smem_u32, mbar_u32, tid,
                     wm, wn, lane, dummy);

    const bool mirror = (ti != tj);
    uint32_t* tD = g_P + ((size_t)((b * 16 + ti) * 64 + tj * 4 + wn)) * TILE_U32;
#pragma unroll
    for (int mt = 0; mt < 4; mt++) {
        uint32_t* tM = mirror
            ? g_P + ((size_t)((b * 16 + tj) * 64 + ti * 4 + wm * 2 + (mt >> 1))) *
                    TILE_U32
            : nullptr;
#pragma unroll
        for (int nt = 0; nt < 4; nt++) {
            __half2 h0 = __floats2half2_rn(__expf(c[mt][nt][0] - 1.0f),
                                           __expf(c[mt][nt][1] - 1.0f));
            __half2 h1 = __floats2half2_rn(__expf(c[mt][nt][2] - 1.0f),
                                           __expf(c[mt][nt][3] - 1.0f));
            const int ia = (((nt >> 1) * 8 + wm * 4 + mt) * 4 + (nt & 1) * 2) * 32
                           + lane;
            tD[ia]      = *(uint32_t*)&h0;   // rows r..r+7 half-pair
            tD[ia + 32] = *(uint32_t*)&h1;   // rows r+8..r+15
            if (mirror) {
                uint32_t t0 = movmat(*(uint32_t*)&h0);
                uint32_t t1 = movmat(*(uint32_t*)&h1);
                const int im = ((((mt & 1)) * 8 + wn * 2 + (nt >> 1)) * 4 +
                                (nt & 1)) * 32 + lane;
                tM[im]      = t0;
                tM[im + 64] = t1;            // q+1 within same ks: reg +2
            }
        }
    }
}

// ------- kernel: GEMM2  out = (P @ x) / rowsum(P) --------------------------
__global__ __launch_bounds__(256, 2) void gemm2_kernel(float* __restrict__ out) {
    extern __shared__ __align__(128) uint32_t smem[];
    __shared__ __align__(8) unsigned long long mbars[3];
    const uint32_t smem_u32 = (uint32_t)__cvta_generic_to_shared(smem);
    const uint32_t mbar_u32 = (uint32_t)__cvta_generic_to_shared(mbars);
    const int b = blockIdx.z, mb = blockIdx.y, nb = blockIdx.x;
    const int tid = threadIdx.x, wid = tid >> 5, lane = tid & 31;
    const int wm = wid >> 2, wn = wid & 3;

    if (tid == 0) {
#pragma unroll
        for (int s = 0; s < 3; s++) mbar_init(mbar_u32 + s * 8, 1);
        fence_async();
    }
    __syncthreads();

    const char* Abase =
        (const char*)(g_P + ((size_t)((b * 16 + mb) * 64)) * TILE_U32);
    const char* Bbase =
        (const char*)(g_xT + ((size_t)((b * 4 + nb) * 64)) * TILE_U32);

    float c[4][4][4];
#pragma unroll
    for (int i = 0; i < 4; i++)
#pragma unroll
        for (int j = 0; j < 4; j++)
#pragma unroll
            for (int k = 0; k < 4; k++) c[i][j][k] = 0.f;
    float sumA[8];
#pragma unroll
    for (int i = 0; i < 8; i++) sumA[i] = 0.f;

    gemm_main<true>(Abase, Bbase, SEQ / 32, c, smem, smem_u32, mbar_u32, tid,
                    wm, wn, lane, sumA);

#pragma unroll
    for (int i = 0; i < 8; i++) {
        sumA[i] += __shfl_xor_sync(0xffffffffu, sumA[i], 1);
        sumA[i] += __shfl_xor_sync(0xffffffffu, sumA[i], 2);
    }
    __syncthreads();
    float* rs = (float*)smem;
    if (wn == 0 && (lane & 3) == 0) {
#pragma unroll
        for (int mt = 0; mt < 4; mt++) {
            rs[wm * 64 + mt * 16 + (lane >> 2)]     = sumA[mt * 2];
            rs[wm * 64 + mt * 16 + 8 + (lane >> 2)] = sumA[mt * 2 + 1];
        }
    }
    __syncthreads();

    const int m0 = mb * 128, n0 = nb * 128;
    const int row0 = m0 + wm * 64 + (lane >> 2);
    const int col0 = n0 + wn * 32 + (lane & 3) * 2;
#pragma unroll
    for (int mt = 0; mt < 4; mt++) {
        const int lr = wm * 64 + mt * 16 + (lane >> 2);
        const float ri0 = 1.0f / rs[lr];
        const float ri1 = 1.0f / rs[lr + 8];
        const int r1 = row0 + mt * 16;
#pragma unroll
        for (int nt = 0; nt < 4; nt++) {
            const int cc = col0 + nt * 8;
            float2 w0, w1;
            w0.x = c[mt][nt][0] * ri0;
            w0.y = c[mt][nt][1] * ri0;
            w1.x = c[mt][nt][2] * ri1;
            w1.y = c[mt][nt][3] * ri1;
            *(float2*)&out[((size_t)b * SEQ + r1) * DIM + cc] = w0;
            *(float2*)&out[((size_t)b * SEQ + r1 + 8) * DIM + cc] = w1;
        }
    }
}

// ---------------- launch ----------------
extern "C" void kernel_launch(void* const* d_in, const int* in_sizes, int n_in,
                              void* d_out, int out_size) {
    const float* x = (const float*)d_in[0];
    float* out = (float*)d_out;

    static bool configured = false;
    if (!configured) {
        cudaFuncSetAttribute(gemm1_kernel,
                             cudaFuncAttributeMaxDynamicSharedMemorySize,
                             SMEM_DYN);
        cudaFuncSetAttribute(gemm2_kernel,
                             cudaFuncAttributeMaxDynamicSharedMemorySize,
                             SMEM_DYN);
        configured = true;
    }

    xhat_kernel<<<BATCH * SEQ / 8, 256>>>(x);
    xT_kernel<<<dim3(SEQ / 32, DIM / 32, BATCH), dim3(32, 8)>>>(x);
    gemm1_kernel<<<dim3(NPAIR, 1, BATCH), 256, SMEM_DYN>>>();
    gemm2_kernel<<<dim3(DIM / 128, SEQ / 128, BATCH), 256, SMEM_DYN>>>(out);
}

// round 13
// speedup vs baseline: 1.8985x; 1.0465x over previous
#include <cuda_runtime.h>
#include <cuda_fp16.h>
#include <cstdint>

// Cosine self-attention, fp16 mma.sync m16n8k16.
// R12: fragment-image gmem tiles + cp.async.bulk fill (360us, tensor 56%).
// R13: K-chunk 64 — two consecutive 8KB tiles per bulk copy, halving the
// per-chunk mbar/sync overhead. All image layouts and fragment reads are
// byte-identical to R12.

#define BATCH 16
#define SEQ   2048
#define DIM   512
#define NTILE 16
#define NPAIR 136
#define TILE_U32 2048                 // 128 rows x 32 halves = 8KB
#define TILE_B   8192
#define STAGE_U32 8192                // 2 A-tiles + 2 B-tiles
#define STAGE_B   32768
#define SMEM_DYN  98304               // 3 stages

__device__ __align__(256) uint32_t g_xhA[(size_t)BATCH * 16 * 16 * TILE_U32];
__device__ __align__(256) uint32_t g_xhB[(size_t)BATCH * 16 * 16 * TILE_U32];
__device__ __align__(256) uint32_t g_xT[(size_t)BATCH * 4 * 64 * TILE_U32];
__device__ __align__(256) uint32_t g_P[(size_t)BATCH * 16 * 64 * TILE_U32];

// ---------------- ptx helpers ----------------
__device__ __forceinline__ void mma16(float c[4], const uint32_t a[4],
                                      const uint32_t b[2]) {
    asm volatile(
        "mma.sync.aligned.m16n8k16.row.col.f32.f16.f16.f32 "
        "{%0,%1,%2,%3}, {%4,%5,%6,%7}, {%8,%9}, {%0,%1,%2,%3};"
        : "+f"(c[0]), "+f"(c[1]), "+f"(c[2]), "+f"(c[3])
        : "r"(a[0]), "r"(a[1]), "r"(a[2]), "r"(a[3]), "r"(b[0]), "r"(b[1]));
}
__device__ __forceinline__ uint32_t movmat(uint32_t a) {
    uint32_t d;
    asm("movmatrix.sync.aligned.m8n8.trans.b16 %0, %1;" : "=r"(d) : "r"(a));
    return d;
}
__device__ __forceinline__ void mbar_init(uint32_t mbar, uint32_t cnt) {
    asm volatile("mbarrier.init.shared.b64 [%0], %1;" :: "r"(mbar), "r"(cnt)
                 : "memory");
}
__device__ __forceinline__ void mbar_expect(uint32_t mbar, uint32_t bytes) {
    asm volatile("mbarrier.arrive.expect_tx.shared.b64 _, [%0], %1;"
                 :: "r"(mbar), "r"(bytes) : "memory");
}
__device__ __forceinline__ void mbar_wait(uint32_t mbar, uint32_t parity) {
    asm volatile(
        "{\n\t.reg .pred P1;\n\t"
        "WL_%=:\n\t"
        "mbarrier.try_wait.parity.acquire.cta.shared::cta.b64 P1, [%0], %1, 0x989680;\n\t"
        "@P1 bra.uni WD_%=;\n\t"
        "bra.uni WL_%=;\n\t"
        "WD_%=:\n\t}"
        :: "r"(mbar), "r"(parity) : "memory");
}
__device__ __forceinline__ void bulk_cp(uint32_t dst, const void* src,
                                        uint32_t bytes, uint32_t mbar) {
    asm volatile(
        "cp.async.bulk.shared::cluster.global.mbarrier::complete_tx::bytes "
        "[%0], [%1], %2, [%3];"
        :: "r"(dst), "l"(src), "r"(bytes), "r"(mbar) : "memory");
}
__device__ __forceinline__ void fence_async() {
    asm volatile("fence.proxy.async.shared::cta;" ::: "memory");
}

// ---------- fragment-image index helpers (match R10 sts_stage exactly) -----
__device__ __forceinline__ int a_img_u4(int r, int q) {
    return (((q >> 1) * 8 + (r >> 4)) * 4 + (q & 1) * 2 + ((r >> 3) & 1)) * 32 +
           (r & 7) * 4;
}
__device__ __forceinline__ int b_img_u4(int n, int q) {
    return (((q >> 1) * 16 + (n >> 3)) * 2 + (q & 1)) * 32 + (n & 7) * 4;
}

// ---------------- kernel: xhat -> A-image + B-image tiles ------------------
__global__ void xhat_kernel(const float* __restrict__ x) {
    const int grow = blockIdx.x * 8 + (threadIdx.x >> 5);
    const int lane = threadIdx.x & 31;
    const float4* src = (const float4*)(x + (size_t)grow * DIM) + lane * 4;
    float4 v[4];
    float ss = 0.f;
#pragma unroll
    for (int i = 0; i < 4; i++) {
        v[i] = src[i];
        ss += v[i].x * v[i].x + v[i].y * v[i].y + v[i].z * v[i].z + v[i].w * v[i].w;
    }
#pragma unroll
    for (int m = 16; m; m >>= 1) ss += __shfl_xor_sync(0xffffffffu, ss, m);
    const float s = 1.0f / sqrtf(ss);
    uint4 U[2];
#pragma unroll
    for (int u = 0; u < 2; u++) {
        __half2 h0 = __floats2half2_rn(v[2 * u].x * s, v[2 * u].y * s);
        __half2 h1 = __floats2half2_rn(v[2 * u].z * s, v[2 * u].w * s);
        __half2 h2 = __floats2half2_rn(v[2 * u + 1].x * s, v[2 * u + 1].y * s);
        __half2 h3 = __floats2half2_rn(v[2 * u + 1].z * s, v[2 * u + 1].w * s);
        U[u].x = *(uint32_t*)&h0; U[u].y = *(uint32_t*)&h1;
        U[u].z = *(uint32_t*)&h2; U[u].w = *(uint32_t*)&h3;
    }
    const int b = grow >> 11, r = grow & 2047, rb = r >> 7, rr = r & 127;
    const int c = lane >> 1;
    uint32_t* tA = g_xhA + ((size_t)((b * 16 + rb) * 16 + c)) * TILE_U32;
    uint32_t* tB = g_xhB + ((size_t)((b * 16 + rb) * 16 + c)) * TILE_U32;
#pragma unroll
    for (int u = 0; u < 2; u++) {
        const int q = (lane & 1) * 2 + u;
        *(uint4*)(tA + a_img_u4(rr, q)) = U[u];
        *(uint4*)(tB + b_img_u4(rr, q)) = U[u];
    }
}

// ---------------- kernel: xT -> B-image tiles ------------------------------
__global__ void xT_kernel(const float* __restrict__ x) {
    __shared__ float t[32][33];
    const int b = blockIdx.z, s0 = blockIdx.x * 32, d0 = blockIdx.y * 32;
    const int tx = threadIdx.x, ty = threadIdx.y;
#pragma unroll
    for (int i = 0; i < 4; i++)
        t[ty + 8 * i][tx] = x[((size_t)b * SEQ + s0 + ty + 8 * i) * DIM + d0 + tx];
    __syncthreads();
    const int c  = s0 >> 5;
    const int nb = d0 >> 7;
    const int n  = (d0 & 127) + tx;
    uint32_t* tile = g_xT + ((size_t)((b * 4 + nb) * 64 + c)) * TILE_U32;
#pragma unroll
    for (int i = 0; i < 2; i++) {
        const int u = ty + 8 * i;
        __half2 hv = __floats2half2_rn(t[2 * u][tx], t[2 * u + 1][tx]);
        const int q = u >> 2;
        const int idx = (((q >> 1) * 16 + (n >> 3)) * 2 + (q & 1)) * 32 +
                        (n & 7) * 4 + (u & 3);
        tile[idx] = *(uint32_t*)&hv;
    }
}

// ------------- GEMM core: bulk-fill pipeline + fragment reads --------------
template <bool SUMROWS>
__device__ __forceinline__ void compute_chunk(const uint32_t* Abuf,
                                              const uint32_t* Bbuf,
                                              float c[4][4][4], int wm, int wn,
                                              int lane, float* sumA) {
#pragma unroll
    for (int ks = 0; ks < 2; ks++) {
        uint32_t a[4][4], b[4][2];
#pragma unroll
        for (int mt = 0; mt < 4; mt++) {
            const uint32_t* p = Abuf + ((ks * 8 + wm * 4 + mt) * 4) * 32 + lane;
#pragma unroll
            for (int j = 0; j < 4; j++) a[mt][j] = p[j * 32];
        }
#pragma unroll
        for (int nt = 0; nt < 4; nt++) {
            const uint32_t* p = Bbuf + ((ks * 16 + wn * 4 + nt) * 2) * 32 + lane;
#pragma unroll
            for (int j = 0; j < 2; j++) b[nt][j] = p[j * 32];
        }
        if (SUMROWS && wn == 0) {
#pragma unroll
            for (int mt = 0; mt < 4; mt++) {
                float2 f0 = __half22float2(*(__half2*)&a[mt][0]);
                float2 f2 = __half22float2(*(__half2*)&a[mt][2]);
                sumA[mt * 2] += (f0.x + f0.y) + (f2.x + f2.y);
                float2 f1 = __half22float2(*(__half2*)&a[mt][1]);
                float2 f3 = __half22float2(*(__half2*)&a[mt][3]);
                sumA[mt * 2 + 1] += (f1.x + f1.y) + (f3.x + f3.y);
            }
        }
#pragma unroll
        for (int mt = 0; mt < 4; mt++)
#pragma unroll
            for (int nt = 0; nt < 4; nt++)
                mma16(c[mt][nt], a[mt], b[nt]);
    }
}

// Chunk = 64 K-halves = 2 consecutive 8KB tiles per operand.
template <bool SUMROWS>
__device__ __forceinline__ void gemm_main(const char* Abase, const char* Bbase,
                                          int T, float c[4][4][4],
                                          uint32_t* smem, uint32_t smem_u32,
                                          uint32_t mbar_u32, int tid, int wm,
                                          int wn, int lane, float* sumA) {
    uint32_t ph0 = 0, ph1 = 0, ph2 = 0;
    auto issue = [&](int t) {
        if (tid == 0) {
            const int s = t % 3;
            const uint32_t mb = mbar_u32 + s * 8;
            mbar_expect(mb, STAGE_B);
            bulk_cp(smem_u32 + s * STAGE_B, Abase + (size_t)t * 2 * TILE_B,
                    2 * TILE_B, mb);
            bulk_cp(smem_u32 + s * STAGE_B + 2 * TILE_B,
                    Bbase + (size_t)t * 2 * TILE_B, 2 * TILE_B, mb);
        }
    };
    issue(0);
    if (T > 1) issue(1);
    for (int t = 0; t < T; t++) {
        const int s = t % 3;
        const uint32_t mb = mbar_u32 + s * 8;
        if (s == 0)      { mbar_wait(mb, ph0); ph0 ^= 1; }
        else if (s == 1) { mbar_wait(mb, ph1); ph1 ^= 1; }
        else             { mbar_wait(mb, ph2); ph2 ^= 1; }
        __syncthreads();
        if (t + 2 < T) issue(t + 2);
#pragma unroll
        for (int u = 0; u < 2; u++)
            compute_chunk<SUMROWS>(smem + s * STAGE_U32 + u * TILE_U32,
                                   smem + s * STAGE_U32 + 2 * TILE_U32 +
                                       u * TILE_U32,
                                   c, wm, wn, lane, sumA);
    }
}

// ------- kernel: GEMM1 (symmetric)  P = half(exp(xhat xhat^T - 1)) ---------
__global__ __launch_bounds__(256, 2) void gemm1_kernel() {
    extern __shared__ __align__(128) uint32_t smem[];
    __shared__ __align__(8) unsigned long long mbars[3];
    const uint32_t smem_u32 = (uint32_t)__cvta_generic_to_shared(smem);
    const uint32_t mbar_u32 = (uint32_t)__cvta_generic_to_shared(mbars);
    const int b = blockIdx.z;
    const int idx = blockIdx.x;
    int ti = (int)(NTILE + 0.5f -
                   sqrtf((NTILE + 0.5f) * (NTILE + 0.5f) - 2.0f * idx - 0.25f));
    while (ti * NTILE - ti * (ti - 1) / 2 > idx) ti--;
    while ((ti + 1) * NTILE - (ti + 1) * ti / 2 <= idx) ti++;
    const int tj = ti + (idx - (ti * NTILE - ti * (ti - 1) / 2));

    const int tid = threadIdx.x, wid = tid >> 5, lane = tid & 31;
    const int wm = wid >> 2, wn = wid & 3;

    if (tid == 0) {
#pragma unroll
        for (int s = 0; s < 3; s++) mbar_init(mbar_u32 + s * 8, 1);
        fence_async();
    }
    __syncthreads();

    const char* Abase =
        (const char*)(g_xhA + ((size_t)((b * 16 + ti) * 16)) * TILE_U32);
    const char* Bbase =
        (const char*)(g_xhB + ((size_t)((b * 16 + tj) * 16)) * TILE_U32);

    float c[4][4][4];
#pragma unroll
    for (int i = 0; i < 4; i++)
#pragma unroll
        for (int j = 0; j < 4; j++)
#pragma unroll
            for (int k = 0; k < 4; k++) c[i][j][k] = 0.f;
    float dummy[8];

    gemm_main<false>(Abase, Bbase, DIM / 64, c, smem, smem_u32, mbar_u32, tid,
                     wm, wn, lane, dummy);

    const bool mirror = (ti != tj);
    uint32_t* tD = g_P + ((size_t)((b * 16 + ti) * 64 + tj * 4 + wn)) * TILE_U32;
#pragma unroll
    for (int mt = 0; mt < 4; mt++) {
        uint32_t* tM = mirror
            ? g_P + ((size_t)((b * 16 + tj) * 64 + ti * 4 + wm * 2 + (mt >> 1))) *
                    TILE_U32
            : nullptr;
#pragma unroll
        for (int nt = 0; nt < 4; nt++) {
            __half2 h0 = __floats2half2_rn(__expf(c[mt][nt][0] - 1.0f),
                                           __expf(c[mt][nt][1] - 1.0f));
            __half2 h1 = __floats2half2_rn(__expf(c[mt][nt][2] - 1.0f),
                                           __expf(c[mt][nt][3] - 1.0f));
            const int ia = (((nt >> 1) * 8 + wm * 4 + mt) * 4 + (nt & 1) * 2) * 32
                           + lane;
            tD[ia]      = *(uint32_t*)&h0;
            tD[ia + 32] = *(uint32_t*)&h1;
            if (mirror) {
                uint32_t t0 = movmat(*(uint32_t*)&h0);
                uint32_t t1 = movmat(*(uint32_t*)&h1);
                const int im = ((((mt & 1)) * 8 + wn * 2 + (nt >> 1)) * 4 +
                                (nt & 1)) * 32 + lane;
                tM[im]      = t0;
                tM[im + 64] = t1;
            }
        }
    }
}

// ------- kernel: GEMM2  out = (P @ x) / rowsum(P) --------------------------
__global__ __launch_bounds__(256, 2) void gemm2_kernel(float* __restrict__ out) {
    extern __shared__ __align__(128) uint32_t smem[];
    __shared__ __align__(8) unsigned long long mbars[3];
    const uint32_t smem_u32 = (uint32_t)__cvta_generic_to_shared(smem);
    const uint32_t mbar_u32 = (uint32_t)__cvta_generic_to_shared(mbars);
    const int b = blockIdx.z, mb = blockIdx.y, nb = blockIdx.x;
    const int tid = threadIdx.x, wid = tid >> 5, lane = tid & 31;
    const int wm = wid >> 2, wn = wid & 3;

    if (tid == 0) {
#pragma unroll
        for (int s = 0; s < 3; s++) mbar_init(mbar_u32 + s * 8, 1);
        fence_async();
    }
    __syncthreads();

    const char* Abase =
        (const char*)(g_P + ((size_t)((b * 16 + mb) * 64)) * TILE_U32);
    const char* Bbase =
        (const char*)(g_xT + ((size_t)((b * 4 + nb) * 64)) * TILE_U32);

    float c[4][4][4];
#pragma unroll
    for (int i = 0; i < 4; i++)
#pragma unroll
        for (int j = 0; j < 4; j++)
#pragma unroll
            for (int k = 0; k < 4; k++) c[i][j][k] = 0.f;
    float sumA[8];
#pragma unroll
    for (int i = 0; i < 8; i++) sumA[i] = 0.f;

    gemm_main<true>(Abase, Bbase, SEQ / 64, c, smem, smem_u32, mbar_u32, tid,
                    wm, wn, lane, sumA);

#pragma unroll
    for (int i = 0; i < 8; i++) {
        sumA[i] += __shfl_xor_sync(0xffffffffu, sumA[i], 1);
        sumA[i] += __shfl_xor_sync(0xffffffffu, sumA[i], 2);
    }
    __syncthreads();
    float* rs = (float*)smem;
    if (wn == 0 && (lane & 3) == 0) {
#pragma unroll
        for (int mt = 0; mt < 4; mt++) {
            rs[wm * 64 + mt * 16 + (lane >> 2)]     = sumA[mt * 2];
            rs[wm * 64 + mt * 16 + 8 + (lane >> 2)] = sumA[mt * 2 + 1];
        }
    }
    __syncthreads();

    const int m0 = mb * 128, n0 = nb * 128;
    const int row0 = m0 + wm * 64 + (lane >> 2);
    const int col0 = n0 + wn * 32 + (lane & 3) * 2;
#pragma unroll
    for (int mt = 0; mt < 4; mt++) {
        const int lr = wm * 64 + mt * 16 + (lane >> 2);
        const float ri0 = 1.0f / rs[lr];
        const float ri1 = 1.0f / rs[lr + 8];
        const int r1 = row0 + mt * 16;
#pragma unroll
        for (int nt = 0; nt < 4; nt++) {
            const int cc = col0 + nt * 8;
            float2 w0, w1;
            w0.x = c[mt][nt][0] * ri0;
            w0.y = c[mt][nt][1] * ri0;
            w1.x = c[mt][nt][2] * ri1;
            w1.y = c[mt][nt][3] * ri1;
            *(float2*)&out[((size_t)b * SEQ + r1) * DIM + cc] = w0;
            *(float2*)&out[((size_t)b * SEQ + r1 + 8) * DIM + cc] = w1;
        }
    }
}

// ---------------- launch ----------------
extern "C" void kernel_launch(void* const* d_in, const int* in_sizes, int n_in,
                              void* d_out, int out_size) {
    const float* x = (const float*)d_in[0];
    float* out = (float*)d_out;

    static bool configured = false;
    if (!configured) {
        cudaFuncSetAttribute(gemm1_kernel,
                             cudaFuncAttributeMaxDynamicSharedMemorySize,
                             SMEM_DYN);
        cudaFuncSetAttribute(gemm2_kernel,
                             cudaFuncAttributeMaxDynamicSharedMemorySize,
                             SMEM_DYN);
        configured = true;
    }

    xhat_kernel<<<BATCH * SEQ / 8, 256>>>(x);
    xT_kernel<<<dim3(SEQ / 32, DIM / 32, BATCH), dim3(32, 8)>>>(x);
    gemm1_kernel<<<dim3(NPAIR, 1, BATCH), 256, SMEM_DYN>>>();
    gemm2_kernel<<<dim3(DIM / 128, SEQ / 128, BATCH), 256, SMEM_DYN>>>(out);
}